// round 6
// baseline (speedup 1.0000x reference)
#include <cuda_runtime.h>
#include <cstddef>

// Problem constants (fixed by the dataset)
#define DD 16     // ds_dim
#define NN 32     // number of systems
#define HH 128    // gating hidden width
#define THREADS 416
#define RPT 2     // rows per thread

typedef unsigned long long ull;

// ---- f32x2 packed-math helpers (sm_103a) ----
__device__ __forceinline__ ull pack2(float lo, float hi) {
    ull r; asm("mov.b64 %0, {%1,%2};" : "=l"(r) : "f"(lo), "f"(hi)); return r;
}
__device__ __forceinline__ ull dup2(float v) { return pack2(v, v); }
__device__ __forceinline__ void unpack2(ull v, float& lo, float& hi) {
    asm("mov.b64 {%0,%1}, %2;" : "=f"(lo), "=f"(hi) : "l"(v));
}
__device__ __forceinline__ ull fma2(ull a, ull b, ull c) {
    ull d; asm("fma.rn.f32x2 %0, %1, %2, %3;" : "=l"(d) : "l"(a), "l"(b), "l"(c));
    return d;
}
__device__ __forceinline__ ull add2(ull a, ull b) {
    ull d; asm("add.rn.f32x2 %0, %1, %2;" : "=l"(d) : "l"(a), "l"(b)); return d;
}
__device__ __forceinline__ ull mul2(ull a, ull b) {
    ull d; asm("mul.rn.f32x2 %0, %1, %2;" : "=l"(d) : "l"(a), "l"(b)); return d;
}

// Dynamic smem layout (floats):
//   sW1n [H*D]    -W1[j][d] row-major (d-pairs feed fma2 with diffp)
//   sW2t [H*N]    transposed: sW2t[j*N + n] = W2[n*H + j]
//   sA   [N*D*D]  A = B+C in ORIGINAL [n][k][d] layout (d contiguous)
//   sb1p [H]      b1'[j] = b1[j] + sum_d W1[j][d]*xt[d]
//   sb2  [N], sxt [D]
//   swb  [N*RPT*THREADS]  per-thread normalized softmax weights
#define W_FLOATS (HH*DD + HH*NN + NN*DD*DD + HH + NN + DD)
#define SMEM_FLOATS (W_FLOATS + NN*RPT*THREADS)

__global__ __launch_bounds__(THREADS)
void fused_gated_ds_kernel(
    const float* __restrict__ x_cur,
    const float* __restrict__ W1,
    const float* __restrict__ b1,
    const float* __restrict__ W2,
    const float* __restrict__ b2,
    const float* __restrict__ Bm,
    const float* __restrict__ Cm,
    const float* __restrict__ xt,
    float* __restrict__ out,
    int Btot)
{
    extern __shared__ float smem[];
    float* sW1n = smem;                    // 2048
    float* sW2t = sW1n + HH*DD;            // 4096
    float* sA   = sW2t + HH*NN;            // 8192
    float* sb1p = sA   + NN*DD*DD;         // 128
    float* sb2  = sb1p + HH;               // 32
    float* sxt  = sb2  + NN;               // 16
    float* swb  = smem + W_FLOATS;

    const int tid = threadIdx.x;

    // ---- stage weights ----
    for (int i = tid; i < HH*DD; i += THREADS) sW1n[i] = -W1[i];
    for (int i = tid; i < HH*NN; i += THREADS) {
        int j = i / NN, n = i % NN;
        sW2t[i] = W2[n*HH + j];
    }
    for (int i = tid; i < NN*DD*DD; i += THREADS) sA[i] = Bm[i] + Cm[i];
    if (tid < NN) sb2[tid] = b2[tid];
    if (tid < DD) sxt[tid] = xt[tid];
    __syncthreads();

    // b1'[j] = b1[j] + sum_d W1[j][d]*xt[d]
    if (tid < HH) {
        float s = b1[tid];
        #pragma unroll
        for (int d = 0; d < DD; d++) s += W1[tid*DD + d] * sxt[d];
        sb1p[tid] = s;
    }
    __syncthreads();

    const int base = blockIdx.x * (THREADS * RPT);
    const int r0 = base + tid;
    const int r1 = base + THREADS + tid;
    if (r0 >= Btot) return;
    const bool act1 = (r1 < Btot);

    // ---- diffp[r][dp] = {xt-x} packed over d-pairs (only x-derived state) ----
    ull diffp[RPT][8];
    {
        const float4* xg = reinterpret_cast<const float4*>(x_cur + (size_t)r0 * DD);
        #pragma unroll
        for (int q = 0; q < 4; q++) {
            float4 v = xg[q];
            diffp[0][2*q]   = pack2(sxt[4*q+0] - v.x, sxt[4*q+1] - v.y);
            diffp[0][2*q+1] = pack2(sxt[4*q+2] - v.z, sxt[4*q+3] - v.w);
        }
    }
    if (act1) {
        const float4* xg = reinterpret_cast<const float4*>(x_cur + (size_t)r1 * DD);
        #pragma unroll
        for (int q = 0; q < 4; q++) {
            float4 v = xg[q];
            diffp[1][2*q]   = pack2(sxt[4*q+0] - v.x, sxt[4*q+1] - v.y);
            diffp[1][2*q+1] = pack2(sxt[4*q+2] - v.z, sxt[4*q+3] - v.w);
        }
    } else {
        #pragma unroll
        for (int i = 0; i < 8; i++) diffp[1][i] = 0ULL;
    }

    // ---- logits packed over n-pairs ----
    ull Lp[RPT][16];
    {
        const ulonglong2* b2p = reinterpret_cast<const ulonglong2*>(sb2);
        #pragma unroll
        for (int q = 0; q < 8; q++) {
            ulonglong2 v = b2p[q];
            Lp[0][2*q] = v.x; Lp[0][2*q+1] = v.y;
            Lp[1][2*q] = v.x; Lp[1][2*q+1] = v.y;
        }
    }

    // ---- fused GEMM1 (on diff, bias-folded, relu) + GEMM2 ----
    #pragma unroll 2
    for (int j = 0; j < HH; j++) {
        const ulonglong2* w1p = reinterpret_cast<const ulonglong2*>(sW1n + j*DD);
        ulonglong2 wA = w1p[0], wB = w1p[1], wC = w1p[2], wD = w1p[3];
        const float bj = sb1p[j];
        ull hd[RPT];
        #pragma unroll
        for (int r = 0; r < RPT; r++) {
            ull s0 = fma2(wA.x, diffp[r][0], 0ULL);
            ull s1 = fma2(wA.y, diffp[r][1], 0ULL);
            s0 = fma2(wB.x, diffp[r][2], s0);
            s1 = fma2(wB.y, diffp[r][3], s1);
            s0 = fma2(wC.x, diffp[r][4], s0);
            s1 = fma2(wC.y, diffp[r][5], s1);
            s0 = fma2(wD.x, diffp[r][6], s0);
            s1 = fma2(wD.y, diffp[r][7], s1);
            ull s = add2(s0, s1);
            float lo, hi; unpack2(s, lo, hi);
            hd[r] = dup2(fmaxf(lo + hi + bj, 0.0f));
        }
        const ulonglong2* w2p = reinterpret_cast<const ulonglong2*>(sW2t + j*NN);
        #pragma unroll
        for (int q = 0; q < 8; q++) {
            ulonglong2 wv = w2p[q];
            #pragma unroll
            for (int r = 0; r < RPT; r++) {
                Lp[r][2*q]   = fma2(wv.x, hd[r], Lp[r][2*q]);
                Lp[r][2*q+1] = fma2(wv.y, hd[r], Lp[r][2*q+1]);
            }
        }
    }

    // ---- softmax per row; store normalized weights (Lp dies) ----
    #pragma unroll
    for (int r = 0; r < RPT; r++) {
        float ev[NN];
        #pragma unroll
        for (int i = 0; i < 16; i++) unpack2(Lp[r][i], ev[2*i], ev[2*i+1]);
        float m = ev[0];
        #pragma unroll
        for (int n = 1; n < NN; n++) m = fmaxf(m, ev[n]);
        float s = 0.0f;
        #pragma unroll
        for (int n = 0; n < NN; n++) { ev[n] = __expf(ev[n] - m); s += ev[n]; }
        const float inv = 1.0f / s;
        #pragma unroll
        for (int n = 0; n < NN; n++) swb[(n*RPT + r)*THREADS + tid] = ev[n] * inv;
    }

    // ---- epilogue, packed over d, two k-passes (k 0..7, 8..15) ----
    // outpair[r][kk] accumulates {sum over even d, sum over odd d}
    #pragma unroll
    for (int pass = 0; pass < 2; pass++) {
        const int k0 = pass * 8;
        ull outpair[RPT][8];
        #pragma unroll
        for (int r = 0; r < RPT; r++)
            #pragma unroll
            for (int kk = 0; kk < 8; kk++) outpair[r][kk] = 0ULL;

        #pragma unroll 1
        for (int n = 0; n < NN; n++) {
            // per-n scaled diff: zp = w_n * diffp
            ull zp[RPT][8];
            #pragma unroll
            for (int r = 0; r < RPT; r++) {
                const ull wd = dup2(swb[(n*RPT + r)*THREADS + tid]);
                #pragma unroll
                for (int dp = 0; dp < 8; dp++)
                    zp[r][dp] = mul2(wd, diffp[r][dp]);
            }
            const ulonglong2* ap =
                reinterpret_cast<const ulonglong2*>(sA + n*DD*DD + k0*DD);
            #pragma unroll
            for (int kk = 0; kk < 8; kk++) {
                ulonglong2 a0 = ap[4*kk + 0];   // d-pairs 0,1
                ulonglong2 a1 = ap[4*kk + 1];   // d-pairs 2,3
                ulonglong2 a2 = ap[4*kk + 2];   // d-pairs 4,5
                ulonglong2 a3 = ap[4*kk + 3];   // d-pairs 6,7
                #pragma unroll
                for (int r = 0; r < RPT; r++) {
                    ull acc = outpair[r][kk];
                    acc = fma2(a0.x, zp[r][0], acc);
                    acc = fma2(a0.y, zp[r][1], acc);
                    acc = fma2(a1.x, zp[r][2], acc);
                    acc = fma2(a1.y, zp[r][3], acc);
                    acc = fma2(a2.x, zp[r][4], acc);
                    acc = fma2(a2.y, zp[r][5], acc);
                    acc = fma2(a3.x, zp[r][6], acc);
                    acc = fma2(a3.y, zp[r][7], acc);
                    outpair[r][kk] = acc;
                }
            }
        }

        // horizontal add + store this pass's 8 outputs per row
        {
            float o[8];
            #pragma unroll
            for (int kk = 0; kk < 8; kk++) {
                float lo, hi; unpack2(outpair[0][kk], lo, hi);
                o[kk] = lo + hi;
            }
            float4* og = reinterpret_cast<float4*>(out + (size_t)r0 * DD + k0);
            og[0] = make_float4(o[0], o[1], o[2], o[3]);
            og[1] = make_float4(o[4], o[5], o[6], o[7]);
        }
        if (act1) {
            float o[8];
            #pragma unroll
            for (int kk = 0; kk < 8; kk++) {
                float lo, hi; unpack2(outpair[1][kk], lo, hi);
                o[kk] = lo + hi;
            }
            float4* og = reinterpret_cast<float4*>(out + (size_t)r1 * DD + k0);
            og[0] = make_float4(o[0], o[1], o[2], o[3]);
            og[1] = make_float4(o[4], o[5], o[6], o[7]);
        }
    }
}

extern "C" void kernel_launch(void* const* d_in, const int* in_sizes, int n_in,
                              void* d_out, int out_size)
{
    const float* x_cur = (const float*)d_in[0];
    const float* W1    = (const float*)d_in[1];
    const float* b1    = (const float*)d_in[2];
    const float* W2    = (const float*)d_in[3];
    const float* b2    = (const float*)d_in[4];
    const float* Bm    = (const float*)d_in[5];
    const float* Cm    = (const float*)d_in[6];
    const float* xt    = (const float*)d_in[7];
    float* out = (float*)d_out;

    const int Btot = in_sizes[0] / DD;
    const size_t smem_bytes = (size_t)SMEM_FLOATS * sizeof(float);

    cudaFuncSetAttribute(fused_gated_ds_kernel,
                         cudaFuncAttributeMaxDynamicSharedMemorySize,
                         (int)smem_bytes);

    const int rows_per_cta = THREADS * RPT;
    const int grid = (Btot + rows_per_cta - 1) / rows_per_cta;
    fused_gated_ds_kernel<<<grid, THREADS, smem_bytes>>>(
        x_cur, W1, b1, W2, b2, Bm, Cm, xt, out, Btot);
}